// round 1
// baseline (speedup 1.0000x reference)
#include <cuda_runtime.h>
#include <math.h>
#include <stdint.h>

#define GN 4096
#define UN 100000
#define IN_ 8192
#define FN 128
#define MN 8192
#define NNZ_RUI 500000
#define NNZ_RGU 8192
#define NNZ_RGI 200000

// ---------------- scratch (device globals: no allocations allowed) ----------
__device__ float g_rui_ei[(size_t)UN * FN];   // rui @ E_i            [U,F]
__device__ float g_rgu_t [(size_t)UN * FN];   // rgu^T @ E_g          [U,F]
__device__ float g_rgi_t [(size_t)IN_ * FN];  // rgi^T @ E_g          [I,F]
__device__ float g_rui_t [(size_t)IN_ * FN];  // rui^T @ E_u          [I,F]
__device__ float g_rgi_ei[(size_t)GN * FN];   // rgi @ E_i            [G,F]
__device__ float g_rgu_eu[(size_t)GN * FN];   // rgu @ E_u            [G,F]
__device__ float g_att_g [(size_t)GN * FN];   // rgi @ attentive_item [G,F]
__device__ float g_members[(size_t)MN * FN];  // user_emb[member_idx] [M,F]
__device__ float g_attitem[(size_t)IN_ * FN]; // attentive_item       [I,F]
__device__ float g_inv[MN];                   // per-member softmax 1/sum
__device__ float g_S[(size_t)MN * IN_];       // scores, TRANSPOSED: S[m][i]

// ---------------- gather members --------------------------------------------
__global__ void gather_members_k(const float* __restrict__ user,
                                 const int* __restrict__ idx) {
    int t = blockIdx.x * blockDim.x + threadIdx.x;
    if (t < MN * 32) {
        int m = t >> 5, j = t & 31;
        ((float4*)g_members)[t] =
            ((const float4*)(user + (size_t)idx[m] * FN))[j];
    }
}

// ---------------- GEMM1: S[m][i] = members[m] . item[i]  (NT, K=128) --------
// BM=BN=128, BK=16, 256 thr, 8x8 per thread
__global__ __launch_bounds__(256) void gemm_s_k(const float* __restrict__ Bitem) {
    __shared__ float As[16][128];
    __shared__ float Bs[16][128];
    int bm = blockIdx.y * 128, bn = blockIdx.x * 128;
    int tid = threadIdx.x;
    int ty = tid >> 4, tx = tid & 15;
    float acc[8][8];
#pragma unroll
    for (int i = 0; i < 8; i++)
#pragma unroll
        for (int j = 0; j < 8; j++) acc[i][j] = 0.f;

    for (int k0 = 0; k0 < FN; k0 += 16) {
#pragma unroll
        for (int it = 0; it < 2; ++it) {
            int l = tid + it * 256;
            int r = l >> 2, kq = (l & 3) * 4;
            float4 av = *(const float4*)(g_members + (size_t)(bm + r) * FN + k0 + kq);
            As[kq + 0][r] = av.x; As[kq + 1][r] = av.y;
            As[kq + 2][r] = av.z; As[kq + 3][r] = av.w;
            float4 bv = *(const float4*)(Bitem + (size_t)(bn + r) * FN + k0 + kq);
            Bs[kq + 0][r] = bv.x; Bs[kq + 1][r] = bv.y;
            Bs[kq + 2][r] = bv.z; Bs[kq + 3][r] = bv.w;
        }
        __syncthreads();
#pragma unroll
        for (int kk = 0; kk < 16; ++kk) {
            float4 a0 = *(const float4*)&As[kk][ty * 8];
            float4 a1 = *(const float4*)&As[kk][ty * 8 + 4];
            float4 b0 = *(const float4*)&Bs[kk][tx * 8];
            float4 b1 = *(const float4*)&Bs[kk][tx * 8 + 4];
            float ar[8] = {a0.x, a0.y, a0.z, a0.w, a1.x, a1.y, a1.z, a1.w};
            float br[8] = {b0.x, b0.y, b0.z, b0.w, b1.x, b1.y, b1.z, b1.w};
#pragma unroll
            for (int i = 0; i < 8; i++)
#pragma unroll
                for (int j = 0; j < 8; j++) acc[i][j] += ar[i] * br[j];
        }
        __syncthreads();
    }
#pragma unroll
    for (int i = 0; i < 8; i++) {
        size_t ro = (size_t)(bm + ty * 8 + i) * IN_ + bn + tx * 8;
        float4 v0 = {acc[i][0], acc[i][1], acc[i][2], acc[i][3]};
        float4 v1 = {acc[i][4], acc[i][5], acc[i][6], acc[i][7]};
        *(float4*)(g_S + ro) = v0;
        *(float4*)(g_S + ro + 4) = v1;
    }
}

// ---------------- row softmax of S (= col softmax of e_u), store exp + 1/sum
__global__ __launch_bounds__(256) void softmax_k() {
    float4* row = (float4*)(g_S + (size_t)blockIdx.x * IN_);
    int tid = threadIdx.x;
    __shared__ float red[8];
    float mx = -1e30f;
    for (int c = tid; c < IN_ / 4; c += 256) {
        float4 v = row[c];
        mx = fmaxf(mx, fmaxf(fmaxf(v.x, v.y), fmaxf(v.z, v.w)));
    }
#pragma unroll
    for (int o = 16; o; o >>= 1) mx = fmaxf(mx, __shfl_xor_sync(0xffffffffu, mx, o));
    if ((tid & 31) == 0) red[tid >> 5] = mx;
    __syncthreads();
    mx = red[0];
#pragma unroll
    for (int w = 1; w < 8; w++) mx = fmaxf(mx, red[w]);

    float s = 0.f;
    for (int c = tid; c < IN_ / 4; c += 256) {
        float4 v = row[c];
        v.x = __expf(v.x - mx); v.y = __expf(v.y - mx);
        v.z = __expf(v.z - mx); v.w = __expf(v.w - mx);
        s += v.x + v.y + v.z + v.w;
        row[c] = v;
    }
#pragma unroll
    for (int o = 16; o; o >>= 1) s += __shfl_xor_sync(0xffffffffu, s, o);
    __syncthreads();
    if ((tid & 31) == 0) red[tid >> 5] = s;
    __syncthreads();
    if (tid == 0) {
        float tot = 0.f;
#pragma unroll
        for (int w = 0; w < 8; w++) tot += red[w];
        g_inv[blockIdx.x] = 1.0f / tot;
    }
}

// ---------------- GEMM2: attitem[i][f] = (sum_m S[m][i]*inv[m]*mem[m][f])*item[i][f]
// BM=64 (i), BN=128 (f), BK=16 (m), 256 thr, 4x8 per thread
__global__ __launch_bounds__(256) void attn2_k(const float* __restrict__ item) {
    __shared__ float As[16][64];
    __shared__ float Bs[16][128];
    int bi = blockIdx.x * 64;
    int tid = threadIdx.x, ty = tid >> 4, tx = tid & 15;
    float acc[4][8];
#pragma unroll
    for (int i = 0; i < 4; i++)
#pragma unroll
        for (int j = 0; j < 8; j++) acc[i][j] = 0.f;

    for (int m0 = 0; m0 < MN; m0 += 16) {
        {
            int kk = tid >> 4, i4 = tid & 15;
            float4 v = *(const float4*)(g_S + (size_t)(m0 + kk) * IN_ + bi + i4 * 4);
            *(float4*)&As[kk][i4 * 4] = v;
        }
#pragma unroll
        for (int it = 0; it < 2; ++it) {
            int l = tid + it * 256;
            int kk = l >> 5, f4 = l & 31;
            float sc = g_inv[m0 + kk];
            float4 v = *(const float4*)(g_members + (size_t)(m0 + kk) * FN + f4 * 4);
            v.x *= sc; v.y *= sc; v.z *= sc; v.w *= sc;
            *(float4*)&Bs[kk][f4 * 4] = v;
        }
        __syncthreads();
#pragma unroll
        for (int kk = 0; kk < 16; ++kk) {
            float4 a = *(const float4*)&As[kk][ty * 4];
            float4 b0 = *(const float4*)&Bs[kk][tx * 8];
            float4 b1 = *(const float4*)&Bs[kk][tx * 8 + 4];
            float ar[4] = {a.x, a.y, a.z, a.w};
            float br[8] = {b0.x, b0.y, b0.z, b0.w, b1.x, b1.y, b1.z, b1.w};
#pragma unroll
            for (int i = 0; i < 4; i++)
#pragma unroll
                for (int j = 0; j < 8; j++) acc[i][j] += ar[i] * br[j];
        }
        __syncthreads();
    }
#pragma unroll
    for (int i = 0; i < 4; i++) {
        size_t ro = (size_t)(bi + ty * 4 + i) * FN + tx * 8;
        float4 e0 = *(const float4*)(item + ro);
        float4 e1 = *(const float4*)(item + ro + 4);
        float4 v0 = {acc[i][0] * e0.x, acc[i][1] * e0.y, acc[i][2] * e0.z, acc[i][3] * e0.w};
        float4 v1 = {acc[i][4] * e1.x, acc[i][5] * e1.y, acc[i][6] * e1.z, acc[i][7] * e1.w};
        *(float4*)(g_attitem + ro) = v0;
        *(float4*)(g_attitem + ro + 4) = v1;
    }
}

// ---------------- COO SpMM with atomics: out[row] += val * X[col] -----------
__global__ void spmm_k(const int* __restrict__ rows, const int* __restrict__ cols,
                       const float* __restrict__ vals, const float* __restrict__ X,
                       float* __restrict__ out, int nnz) {
    int w = (int)((blockIdx.x * 256u + threadIdx.x) >> 5);
    if (w >= nnz) return;
    int lane = threadIdx.x & 31;
    int r = rows[w], c = cols[w];
    float v = vals[w];
    float4 x = ((const float4*)(X + (size_t)c * FN))[lane];
    float* o = out + (size_t)r * FN + lane * 4;
    atomicAdd(o + 0, v * x.x);
    atomicAdd(o + 1, v * x.y);
    atomicAdd(o + 2, v * x.z);
    atomicAdd(o + 3, v * x.w);
}

// ---------------- fused lin5 + bias + LeakyReLU + row L2 norm ---------------
// y = sum_k xs_k @ W_k^T + sum_k b_k ; xs synthesized on the fly.
// MODE 0 (user/item): xs = [e, a, a*e, b*e, b]
// MODE 1 (group)    : xs = [e, a, b*e, a*e, c]
// GEMM: [Md, 640] @ [640, 128]; BM=64, BN=128, BK=16, 256 thr, 4x8/thread
template <int MODE>
__global__ __launch_bounds__(256) void lin5_k(
    const float* __restrict__ E, const float* __restrict__ A,
    const float* __restrict__ B, const float* __restrict__ C4,
    const float* __restrict__ W, const float* __restrict__ bias,
    float* __restrict__ out, int Md) {
    __shared__ float As[16][68];
    __shared__ float Bs[16][132];
    __shared__ float bsum[128];
    __shared__ float rs[64][17];
    int tid = threadIdx.x, ty = tid >> 4, tx = tid & 15;
    int bm = blockIdx.x * 64;
    if (tid < 128)
        bsum[tid] = bias[tid] + bias[128 + tid] + bias[256 + tid] +
                    bias[384 + tid] + bias[512 + tid];
    float acc[4][8];
#pragma unroll
    for (int i = 0; i < 4; i++)
#pragma unroll
        for (int j = 0; j < 8; j++) acc[i][j] = 0.f;

    for (int k0 = 0; k0 < 640; k0 += 16) {
        int k = k0 >> 7, fb = k0 & 127;
#pragma unroll
        for (int it = 0; it < 4; ++it) {
            int l = tid + it * 256;
            int kt = l & 15, mm = l >> 4;
            int m = bm + mm;
            float v = 0.f;
            if (m < Md) {
                size_t off = (size_t)m * FN + fb + kt;
                switch (k) {
                    case 0: v = E[off]; break;
                    case 1: v = A[off]; break;
                    case 2: v = (MODE == 0 ? A[off] : B[off]) * E[off]; break;
                    case 3: v = (MODE == 0 ? B[off] : A[off]) * E[off]; break;
                    default: v = (MODE == 0 ? B[off] : C4[off]); break;
                }
            }
            As[kt][mm] = v;
        }
#pragma unroll
        for (int it = 0; it < 8; ++it) {
            int l = tid + it * 256;
            int kt = l & 15, n = l >> 4;
            Bs[kt][n] = W[(size_t)k * 16384 + (size_t)n * FN + fb + kt];
        }
        __syncthreads();
#pragma unroll
        for (int kk = 0; kk < 16; ++kk) {
            float4 a = *(const float4*)&As[kk][ty * 4];
            float4 b0 = *(const float4*)&Bs[kk][tx * 8];
            float4 b1 = *(const float4*)&Bs[kk][tx * 8 + 4];
            float ar[4] = {a.x, a.y, a.z, a.w};
            float br[8] = {b0.x, b0.y, b0.z, b0.w, b1.x, b1.y, b1.z, b1.w};
#pragma unroll
            for (int i = 0; i < 4; i++)
#pragma unroll
                for (int j = 0; j < 8; j++) acc[i][j] += ar[i] * br[j];
        }
        __syncthreads();
    }
    // epilogue: bias + LeakyReLU + row L2 norm
    float sq[4] = {0.f, 0.f, 0.f, 0.f};
#pragma unroll
    for (int i = 0; i < 4; i++)
#pragma unroll
        for (int j = 0; j < 8; j++) {
            float v = acc[i][j] + bsum[tx * 8 + j];
            v = (v >= 0.f) ? v : 0.01f * v;
            acc[i][j] = v;
            sq[i] += v * v;
        }
#pragma unroll
    for (int i = 0; i < 4; i++) rs[ty * 4 + i][tx] = sq[i];
    __syncthreads();
#pragma unroll
    for (int i = 0; i < 4; i++) {
        int m = bm + ty * 4 + i;
        if (m < Md) {
            float s = 0.f;
#pragma unroll
            for (int t = 0; t < 16; t++) s += rs[ty * 4 + i][t];
            float inv = 1.0f / fmaxf(sqrtf(s), 1e-12f);
            float4 v0 = {acc[i][0] * inv, acc[i][1] * inv, acc[i][2] * inv, acc[i][3] * inv};
            float4 v1 = {acc[i][4] * inv, acc[i][5] * inv, acc[i][6] * inv, acc[i][7] * inv};
            size_t ro = (size_t)m * FN + tx * 8;
            *(float4*)(out + ro) = v0;
            *(float4*)(out + ro + 4) = v1;
        }
    }
}

// ---------------- launch ----------------------------------------------------
extern "C" void kernel_launch(void* const* d_in, const int* in_sizes, int n_in,
                              void* d_out, int out_size) {
    const float* group_emb = (const float*)d_in[0];
    const float* user_emb  = (const float*)d_in[1];
    const float* item_emb  = (const float*)d_in[2];
    const int*   member_idx = (const int*)d_in[3];
    const int*   rui_rows = (const int*)d_in[4];
    const int*   rui_cols = (const int*)d_in[5];
    const float* rui_vals = (const float*)d_in[6];
    const int*   rgu_rows = (const int*)d_in[7];
    const int*   rgu_cols = (const int*)d_in[8];
    const float* rgu_vals = (const float*)d_in[9];
    const int*   rgi_rows = (const int*)d_in[10];
    const int*   rgi_cols = (const int*)d_in[11];
    const float* rgi_vals = (const float*)d_in[12];
    const float* Wu = (const float*)d_in[13];
    const float* bu = (const float*)d_in[14];
    const float* Wi = (const float*)d_in[15];
    const float* bi = (const float*)d_in[16];
    const float* Wg = (const float*)d_in[17];
    const float* bg = (const float*)d_in[18];

    float* out = (float*)d_out;
    float* out_g = out;
    float* out_u = out + (size_t)GN * FN;
    float* out_i = out + (size_t)(GN + UN) * FN;

    void *p_rui_ei, *p_rgu_t, *p_rgi_t, *p_rui_t, *p_rgi_ei, *p_rgu_eu,
         *p_att_g, *p_attitem;
    cudaGetSymbolAddress(&p_rui_ei, g_rui_ei);
    cudaGetSymbolAddress(&p_rgu_t, g_rgu_t);
    cudaGetSymbolAddress(&p_rgi_t, g_rgi_t);
    cudaGetSymbolAddress(&p_rui_t, g_rui_t);
    cudaGetSymbolAddress(&p_rgi_ei, g_rgi_ei);
    cudaGetSymbolAddress(&p_rgu_eu, g_rgu_eu);
    cudaGetSymbolAddress(&p_att_g, g_att_g);
    cudaGetSymbolAddress(&p_attitem, g_attitem);

    cudaMemsetAsync(p_rui_ei, 0, sizeof(float) * (size_t)UN * FN);
    cudaMemsetAsync(p_rgu_t, 0, sizeof(float) * (size_t)UN * FN);
    cudaMemsetAsync(p_rgi_t, 0, sizeof(float) * (size_t)IN_ * FN);
    cudaMemsetAsync(p_rui_t, 0, sizeof(float) * (size_t)IN_ * FN);
    cudaMemsetAsync(p_rgi_ei, 0, sizeof(float) * (size_t)GN * FN);
    cudaMemsetAsync(p_rgu_eu, 0, sizeof(float) * (size_t)GN * FN);
    cudaMemsetAsync(p_att_g, 0, sizeof(float) * (size_t)GN * FN);

    // attention path
    gather_members_k<<<(MN * 32 + 255) / 256, 256>>>(user_emb, member_idx);
    gemm_s_k<<<dim3(IN_ / 128, MN / 128), 256>>>(item_emb);
    softmax_k<<<MN, 256>>>();
    attn2_k<<<IN_ / 64, 256>>>(item_emb);

    // sparse aggregations (atomic scatter)
    spmm_k<<<(NNZ_RUI + 7) / 8, 256>>>(rui_rows, rui_cols, rui_vals, item_emb,
                                       (float*)p_rui_ei, NNZ_RUI);
    spmm_k<<<(NNZ_RGU + 7) / 8, 256>>>(rgu_cols, rgu_rows, rgu_vals, group_emb,
                                       (float*)p_rgu_t, NNZ_RGU);
    spmm_k<<<(NNZ_RGI + 7) / 8, 256>>>(rgi_cols, rgi_rows, rgi_vals, group_emb,
                                       (float*)p_rgi_t, NNZ_RGI);
    spmm_k<<<(NNZ_RUI + 7) / 8, 256>>>(rui_cols, rui_rows, rui_vals, user_emb,
                                       (float*)p_rui_t, NNZ_RUI);
    spmm_k<<<(NNZ_RGI + 7) / 8, 256>>>(rgi_rows, rgi_cols, rgi_vals, item_emb,
                                       (float*)p_rgi_ei, NNZ_RGI);
    spmm_k<<<(NNZ_RGU + 7) / 8, 256>>>(rgu_rows, rgu_cols, rgu_vals, user_emb,
                                       (float*)p_rgu_eu, NNZ_RGU);
    spmm_k<<<(NNZ_RGI + 7) / 8, 256>>>(rgi_rows, rgi_cols, rgi_vals,
                                       (const float*)p_attitem,
                                       (float*)p_att_g, NNZ_RGI);

    // fused lin5 + LeakyReLU + L2 norm
    lin5_k<0><<<(UN + 63) / 64, 256>>>(user_emb, (const float*)p_rui_ei,
                                       (const float*)p_rgu_t, nullptr, Wu, bu,
                                       out_u, UN);
    lin5_k<0><<<IN_ / 64, 256>>>(item_emb, (const float*)p_rui_t,
                                 (const float*)p_rgi_t, nullptr, Wi, bi,
                                 out_i, IN_);
    lin5_k<1><<<GN / 64, 256>>>(group_emb, (const float*)p_rgi_ei,
                                (const float*)p_rgu_eu, (const float*)p_att_g,
                                Wg, bg, out_g, GN);
}